// round 14
// baseline (speedup 1.0000x reference)
#include <cuda_runtime.h>

#define FULL 0xFFFFFFFFu
static const int NROW = 25200;
static const int BIMG = 8;
static const int NBIN = 1024;
static const int KC   = 512;
static const int KP   = 1024;
static const int TILE = 112;               // 25200 = 225 * 112
static const int NTILE = NROW / TILE;      // 225

// ---------------- global scratch (static __device__, no allocation) -------
__device__ __align__(16) unsigned long long g_keys[2][BIMG][NROW];
__device__ int            g_hist[16][NBIN];
__device__ int            g_done[16];      // score tiles finished per segment
__device__ float4         g_box [2][BIMG][KP];
__device__ unsigned char  g_cls [2][BIMG][KP];
__device__ unsigned char  g_keep[2][BIMG][KP];   // only [0] (clean) is published
__device__ int            g_flag[BIMG];    // clean segment done flags
__device__ float          g_tot[2];
__device__ int            g_cnt;

__device__ __forceinline__ float iou_rn(float4 a, float4 b) {
    float tlx = fmaxf(a.x, b.x), tly = fmaxf(a.y, b.y);
    float brx = fminf(a.z, b.z), bry = fminf(a.w, b.w);
    float w = fmaxf(__fsub_rn(brx, tlx), 0.0f);
    float h = fmaxf(__fsub_rn(bry, tly), 0.0f);
    float inter = __fmul_rn(w, h);
    float aa = __fmul_rn(__fsub_rn(a.z, a.x), __fsub_rn(a.w, a.y));
    float ab = __fmul_rn(__fsub_rn(b.z, b.x), __fsub_rn(b.w, b.y));
    float uni = __fsub_rn(__fadd_rn(aa, ab), inter);
    uni = (uni > 0.0f) ? uni : 1.0f;
    return __fdiv_rn(inter, uni);
}

__device__ __forceinline__ int binof(float conf) {
    int b = (int)(__fmul_rn(conf, 1024.0f));
    return b > NBIN - 1 ? NBIN - 1 : (b < 0 ? 0 : b);
}

// biased high-word of the smallest positive float whose bin >= B (exact).
__device__ __forceinline__ unsigned cut_for(int B) {
    if (B <= 0) return 0x80000001u;
    if (B > NBIN - 1) return 0xFFFFFFFFu;
    float g = (float)B / 1024.0f;
    for (;;) {
        float p = __int_as_float(__float_as_int(g) - 1);
        if ((int)(__fmul_rn(p, 1024.0f)) >= B) g = p; else break;
    }
    return __float_as_uint(g) ^ 0x80000000u;
}

// ---------------- K1: tile-staged score / key / histogram ------------------
// seg = blockIdx.y: 0-7 clean (scored first), 8-15 patch.
__global__ void __launch_bounds__(128) k_score(const float* __restrict__ clean,
                                               const float* __restrict__ patch) {
    __shared__ float sd[TILE * 85];
    int seg   = blockIdx.y;
    int which = seg >> 3, img = seg & 7;
    int tile  = blockIdx.x;
    int tid   = threadIdx.x;
    if (seg == 0 && tile == 0 && tid == 0) { g_tot[0] = 0.0f; g_tot[1] = 0.0f; }
    const float* base = (which ? patch : clean)
                      + ((size_t)img * NROW + (size_t)tile * TILE) * 85;
    const float4* b4 = (const float4*)base;
    float4* s4 = (float4*)sd;

    {   // 2380 float4 = 18*128 + 76, MLP-batched
        float4 r[9];
        #pragma unroll
        for (int k = 0; k < 9; k++) r[k] = b4[tid + k * 128];
        #pragma unroll
        for (int k = 0; k < 9; k++) s4[tid + k * 128] = r[k];
        #pragma unroll
        for (int k = 0; k < 9; k++) r[k] = b4[tid + (9 + k) * 128];
        #pragma unroll
        for (int k = 0; k < 9; k++) s4[tid + (9 + k) * 128] = r[k];
        if (tid < 76) s4[tid + 2304] = b4[tid + 2304];
    }
    __syncthreads();

    if (tid < TILE) {
        const float* row = sd + tid * 85;
        float obj = row[4];
        float m0 = row[5], m1 = row[6], m2 = row[7], m3 = row[8];
        #pragma unroll
        for (int c = 9; c < 85; c += 4) {
            m0 = fmaxf(m0, row[c]);     m1 = fmaxf(m1, row[c + 1]);
            m2 = fmaxf(m2, row[c + 2]); m3 = fmaxf(m3, row[c + 3]);
        }
        float conf = __fmul_rn(fmaxf(fmaxf(m0, m1), fmaxf(m2, m3)), obj);
        int r = tile * TILE + tid;
        float TH = which ? 0.001f : 0.25f;
        unsigned long long key = 0ull;
        if (obj > TH && conf > TH) {
            int cls = 0;
            for (int c = 5; c < 85; c++) {
                if (__fmul_rn(row[c], obj) == conf) { cls = c - 5; break; }
            }
            unsigned u = __float_as_uint(conf) ^ 0x80000000u;
            key = ((unsigned long long)u << 32)
                | ((unsigned)(32767 - r) << 7) | (unsigned)cls;
            atomicAdd(&g_hist[seg][binof(conf)], 1);
        }
        g_keys[which][img][r] = key;                    // coalesced
    }
    __threadfence();
    __syncthreads();
    if (tid == 0) atomicAdd(&g_done[seg], 1);           // publish tile
}

// ---------------- K2: threshold + gather + tie + NMS; patch computes loss ---
__global__ void __launch_bounds__(1024) k_select(const float* __restrict__ clean,
                                                 const float* __restrict__ patch,
                                                 float* __restrict__ out) {
    __shared__ union {
        struct {
            unsigned long long skey[KP];
            unsigned long long tie[1024];
            float4 obox[KP];
            short  clslist[80 * 64];
        } sel;
        struct {
            float4 pdiv[KP];
            short  plist[80 * 128];
        } loss;
    } U;
    __shared__ unsigned char keepc[KP];
    __shared__ unsigned char sclz[KP];
    __shared__ int   ccnt[80];
    __shared__ int   wsum[32];
    __shared__ float rs[32], rn2[32];
    __shared__ int   sNeed, sAllin, sNin, sNtie;
    __shared__ unsigned sCutIn, sCutTie;

    int seg = blockIdx.x;
    int which = seg >> 3, img = seg & 7;
    int K = which ? KP : KC;
    const float* src = (which ? patch : clean) + (size_t)img * NROW * 85;
    const unsigned long long* keys = g_keys[which][img];
    int tid = threadIdx.x, lane = tid & 31, w = tid >> 5;

    // --- wait for this segment's scoring to complete (overlapped node) ---
    if (tid == 0) { while (atomicAdd(&g_done[seg], 0) < NTILE) {} }
    __syncthreads();

    // --- Phase A: one bin per thread, descending order ---
    int s = g_hist[seg][NBIN - 1 - tid];
    int inc = s;
    #pragma unroll
    for (int off = 1; off < 32; off <<= 1) {
        int n = __shfl_up_sync(FULL, inc, off);
        if (lane >= off) inc += n;
    }
    if (lane == 31) wsum[w] = inc;
    if (tid == 0) { sNin = 0; sNtie = 0; sAllin = 0; sNeed = 0; }
    if (tid < 80) ccnt[tid] = 0;
    __syncthreads();
    if (w == 0) {
        int v = wsum[lane];
        #pragma unroll
        for (int off = 1; off < 32; off <<= 1) {
            int n = __shfl_up_sync(FULL, v, off);
            if (lane >= off) v += n;
        }
        wsum[lane] = v;
    }
    __syncthreads();
    int wbase = w ? wsum[w - 1] : 0;
    int incl = wbase + inc, excl = incl - s;
    int total = wsum[31];
    if (total <= K) {
        if (tid == 0) {
            sAllin = 1; sCutIn = 0x80000001u; sCutTie = 0x80000001u;
        }
    } else if (excl < K && incl >= K) {           // unique crossing thread
        int T = NBIN - 1 - tid;
        sNeed  = K - excl;
        sCutIn = cut_for(T + 1);
        sCutTie = cut_for(T);
    }
    g_hist[seg][tid] = 0;                          // re-zero for next replay
    __syncthreads();
    int allin = sAllin, need = sNeed;
    unsigned cutIn = sCutIn, cutTie = sCutTie;

    // --- Phase B: gather, 5 keys2/thread/round x 3 rounds, scan-based ---
    const ulonglong2* keys2 = (const ulonglong2*)keys;
    const int NP = NROW / 2;                       // 12600
    for (int it = 0; it < 3; it++) {
        ulonglong2 kk[5];
        bool fin[5][2], fti[5][2];
        int cin = 0, cti = 0;
        #pragma unroll
        for (int q = 0; q < 5; q++) {
            int i = it * 5120 + q * 1024 + tid;
            if (i < NP) kk[q] = keys2[i]; else { kk[q].x = 0; kk[q].y = 0; }
            unsigned ha = (unsigned)(kk[q].x >> 32), hb = (unsigned)(kk[q].y >> 32);
            fin[q][0] = ha >= cutIn;             fin[q][1] = hb >= cutIn;
            fti[q][0] = !fin[q][0] && ha >= cutTie;
            fti[q][1] = !fin[q][1] && hb >= cutTie;
            cin += fin[q][0] + fin[q][1];
            cti += fti[q][0] + fti[q][1];
        }
        int pin = cin, pti = cti;
        #pragma unroll
        for (int off = 1; off < 32; off <<= 1) {
            int a = __shfl_up_sync(FULL, pin, off);
            int b = __shfl_up_sync(FULL, pti, off);
            if (lane >= off) { pin += a; pti += b; }
        }
        int wtotin = __shfl_sync(FULL, pin, 31);
        int wtotti = __shfl_sync(FULL, pti, 31);
        int bin0 = 0, bti0 = 0;
        if (lane == 31) {
            if (wtotin) bin0 = atomicAdd(&sNin, wtotin);
            if (wtotti) bti0 = atomicAdd(&sNtie, wtotti);
        }
        bin0 = __shfl_sync(FULL, bin0, 31);
        bti0 = __shfl_sync(FULL, bti0, 31);
        int pos  = bin0 + pin - cin;
        int posT = bti0 + pti - cti;
        #pragma unroll
        for (int q = 0; q < 5; q++) {
            if (fin[q][0]) U.sel.skey[pos++] = kk[q].x;
            if (fti[q][0] && posT < 1024) U.sel.tie[posT] = kk[q].x;
            posT += fti[q][0];
            if (fin[q][1]) U.sel.skey[pos++] = kk[q].y;
            if (fti[q][1] && posT < 1024) U.sel.tie[posT] = kk[q].y;
            posT += fti[q][1];
        }
    }
    __syncthreads();
    int nin = sNin;
    int S = nin;
    if (!allin && need > 0) {
        // tie resolve by rank-counting (keys distinct, no sort)
        int nt = sNtie; if (nt > 1024) nt = 1024;
        if (tid < nt) {
            unsigned long long k = U.sel.tie[tid];
            int rank = 0;
            for (int j = 0; j < nt; j++) rank += (U.sel.tie[j] > k);
            if (rank < need) U.sel.skey[nin + rank] = k;
        }
        S = nin + need;
    }
    __syncthreads();

    // --- Phase C: per-thread decode (cls from key; 5 loads per row) ---
    if (tid < S) {
        unsigned long long key = U.sel.skey[tid];
        unsigned lo32 = (unsigned)key;
        int cls = (int)(lo32 & 127u);
        int idx = 32767 - (int)((lo32 >> 7) & 32767u);
        const float* rp = src + (size_t)idx * 85;
        float cx = rp[0], cy = rp[1], ww2 = rp[2], hh2 = rp[3];
        float hw = __fmul_rn(ww2, 0.5f), hh = __fmul_rn(hh2, 0.5f);
        float4 pb4, ob;
        pb4.x = __fsub_rn(cx, hw); pb4.y = __fsub_rn(cy, hh);
        pb4.z = __fadd_rn(cx, hw); pb4.w = __fadd_rn(cy, hh);
        float off = (float)cls * 4096.0f;
        ob.x = __fadd_rn(pb4.x, off); ob.y = __fadd_rn(pb4.y, off);
        ob.z = __fadd_rn(pb4.z, off); ob.w = __fadd_rn(pb4.w, off);
        g_box[which][img][tid] = pb4;
        g_cls[which][img][tid] = (unsigned char)cls;
        U.sel.obox[tid] = ob;
        keepc[tid] = 1;
        sclz[tid]  = (unsigned char)cls;
        int p = atomicAdd(&ccnt[cls], 1);
        if (p < 64) U.sel.clslist[cls * 64 + p] = (short)tid;
        else if (which == 0) g_keep[0][img][tid] = 1;  // overflow: kept
    } else {
        keepc[tid] = 0;
    }
    if (which == 0)
        for (int i = S + tid; i < K; i += 1024) g_keep[0][img][i] = 0;
    __syncthreads();

    // --- Phase D: per-class NMS, one warp per class (broadcast-smem) ---
    for (int c = w; c < 80; c += 32) {
        int m = ccnt[c]; if (m > 64) m = 64;
        int base2 = c * 64;
        if (m == 0) continue;
        if (m == 1) {
            if (which == 0 && lane == 0)
                g_keep[0][img][U.sel.clslist[base2]] = 1;
            continue;
        }
        if (m <= 32) {
            int id = (lane < m) ? U.sel.clslist[base2 + lane] : -1;
            unsigned long long myk = (lane < m) ? U.sel.skey[id] : 0ull;
            int rank = 0;
            for (int j = 0; j < m; j++) {                  // broadcast LDS
                unsigned long long kj = U.sel.skey[U.sel.clslist[base2 + j]];
                rank += (kj > myk);
            }
            if (lane < m) U.sel.clslist[base2 + rank] = (short)id;
            __syncwarp();
            int ids = (lane < m) ? U.sel.clslist[base2 + lane] : -1;
            float4 B = (lane < m) ? U.sel.obox[ids] : make_float4(0.f, 0.f, 0.f, 0.f);
            unsigned keepb = (m >= 32) ? FULL : ((1u << m) - 1u);
            for (int a = 0; a < m - 1; a++) {
                if ((keepb >> a) & 1u) {
                    float4 A = U.sel.obox[U.sel.clslist[base2 + a]];  // broadcast
                    bool sup = (lane > a) && (lane < m) && ((keepb >> lane) & 1u)
                               && (iou_rn(A, B) > 0.45f);
                    keepb &= ~__ballot_sync(FULL, sup);
                }
            }
            if (lane < m) {
                unsigned char kb = (unsigned char)((keepb >> lane) & 1u);
                keepc[ids] = kb;
                if (which == 0) g_keep[0][img][ids] = kb;
            }
        } else {
            if (lane == 0) {
                for (int i2 = 1; i2 < m; i2++) {
                    short v = U.sel.clslist[base2 + i2];
                    unsigned long long kv = U.sel.skey[v];
                    int j2 = i2 - 1;
                    while (j2 >= 0 && U.sel.skey[U.sel.clslist[base2 + j2]] < kv) {
                        U.sel.clslist[base2 + j2 + 1] = U.sel.clslist[base2 + j2]; j2--;
                    }
                    U.sel.clslist[base2 + j2 + 1] = v;
                }
            }
            __syncwarp();
            for (int a = 0; a < m - 1; a++) {
                int ta = U.sel.clslist[base2 + a];
                if (keepc[ta]) {
                    float4 A = U.sel.obox[ta];
                    for (int b = a + 1 + lane; b < m; b += 32) {
                        int tb = U.sel.clslist[base2 + b];
                        if (keepc[tb] && iou_rn(A, U.sel.obox[tb]) > 0.45f) keepc[tb] = 0;
                    }
                }
                __syncwarp();
            }
            if (which == 0)
                for (int b = lane; b < m; b += 32) {
                    int tb = U.sel.clslist[base2 + b];
                    g_keep[0][img][tb] = keepc[tb];
                }
        }
    }
    __syncthreads();

    // --- Phase E: clean publishes; patch waits + computes loss ---
    if (which == 0) {
        __threadfence();
        if (tid == 0) {
            atomicExch(&g_flag[img], 1);
            g_done[seg] = 0;                   // reset for next replay
        }
        return;
    }

    if (tid == 0) { while (atomicAdd(&g_flag[img], 0) == 0) {} }
    __syncthreads();                           // clean data now visible
    if (tid < 80) ccnt[tid] = 0;
    __syncthreads();                           // safe to overlay union

    {   // patch class lists from own smem state
        float4 pb = g_box[1][img][tid];
        U.loss.pdiv[tid] = make_float4(__fdiv_rn(pb.x, 640.0f), __fdiv_rn(pb.y, 640.0f),
                                       __fdiv_rn(pb.z, 640.0f), __fdiv_rn(pb.w, 640.0f));
        if (keepc[tid]) {
            int c = sclz[tid];
            int p = atomicAdd(&ccnt[c], 1);
            if (p < 128) U.loss.plist[c * 128 + p] = (short)tid;
        }
    }
    __syncthreads();

    float ss = 0.0f, nn = 0.0f;
    if (tid < KC && g_keep[0][img][tid]) {
        nn = 1.0f;
        int c = g_cls[0][img][tid];
        float4 cb = g_box[0][img][tid];
        float4 cd = make_float4(__fdiv_rn(cb.x, 640.0f), __fdiv_rn(cb.y, 640.0f),
                                __fdiv_rn(cb.z, 640.0f), __fdiv_rn(cb.w, 640.0f));
        float tm = 0.0f;
        int m = ccnt[c]; if (m > 128) m = 128;
        int base2 = c * 128;
        for (int b2 = 0; b2 < m; b2++)
            tm = fmaxf(tm, iou_rn(cd, U.loss.pdiv[U.loss.plist[base2 + b2]]));
        ss = tm;
    }
    #pragma unroll
    for (int off = 16; off; off >>= 1) {
        ss += __shfl_down_sync(FULL, ss, off);
        nn += __shfl_down_sync(FULL, nn, off);
    }
    if (lane == 0) { rs[w] = ss; rn2[w] = nn; }
    __syncthreads();
    if (tid == 0) {
        float Sm = 0.0f, Nm = 0.0f;
        #pragma unroll
        for (int i = 0; i < 32; i++) { Sm += rs[i]; Nm += rn2[i]; }
        atomicAdd(&g_tot[0], Sm);
        atomicAdd(&g_tot[1], Nm);
        __threadfence();
        int old = atomicAdd(&g_cnt, 1);
        if (old == BIMG - 1) {
            float tot = atomicAdd(&g_tot[0], 0.0f);
            float cnt = atomicAdd(&g_tot[1], 0.0f);
            out[0] = (cnt > 0.0f) ? __fsub_rn(1.0f, __fdiv_rn(tot, fmaxf(cnt, 1.0f)))
                                  : 1.0f;
            g_cnt = 0;
        }
        g_flag[img] = 0;
        g_done[seg] = 0;                       // reset for next replay
    }
}

// ---------------- launch: score and select as PARALLEL graph nodes ----------
extern "C" void kernel_launch(void* const* d_in, const int* in_sizes, int n_in,
                              void* d_out, int out_size) {
    const float* clean = (const float*)d_in[0];
    const float* patch = (const float*)d_in[1];

    static cudaStream_t s1 = 0;
    static cudaEvent_t ev_fork = 0, ev_join = 0;
    if (!s1) {                                  // first call is uncaptured
        cudaStreamCreateWithFlags(&s1, cudaStreamNonBlocking);
        cudaEventCreateWithFlags(&ev_fork, cudaEventDisableTiming);
        cudaEventCreateWithFlags(&ev_join, cudaEventDisableTiming);
    }

    cudaEventRecord(ev_fork, 0);                // legacy stream (captured)
    cudaStreamWaitEvent(s1, ev_fork, 0);

    dim3 sgrid(NTILE, 16);                      // clean segs first (y 0-7)
    k_score<<<sgrid, 128>>>(clean, patch);      // node A (default stream)
    k_select<<<16, 1024, 0, s1>>>(clean, patch, (float*)d_out);  // node B (parallel)

    cudaEventRecord(ev_join, s1);
    cudaStreamWaitEvent(0, ev_join, 0);         // join back into captured stream
}

// round 16
// speedup vs baseline: 1.0219x; 1.0219x over previous
#include <cuda_runtime.h>

#define FULL 0xFFFFFFFFu
static const int NROW = 25200;
static const int BIMG = 8;
static const int NBIN = 1024;
static const int KC   = 512;
static const int KP   = 1024;
static const int TILE = 112;               // 25200 = 225 * 112
static const int NTILE = NROW / TILE;      // 225

// seg = which*8 + img;  which: 0 = clean, 1 = patch
__device__ __align__(16) unsigned g_keyhi[16][NROW];   // biased conf bits
__device__ __align__(16) unsigned g_keylo[16][NROW];   // (32767-row)<<7 | cls
__device__ int            g_hist[16][NBIN];
__device__ float4         g_box [2][BIMG][KP];
__device__ unsigned char  g_cls [2][BIMG][KP];
__device__ unsigned char  g_keep[2][BIMG][KP];   // only [0] (clean) published
__device__ int            g_flag[BIMG];    // clean segment done flags
__device__ float          g_tot[2];
__device__ int            g_cnt;

__device__ __forceinline__ float iou_rn(float4 a, float4 b) {
    float tlx = fmaxf(a.x, b.x), tly = fmaxf(a.y, b.y);
    float brx = fminf(a.z, b.z), bry = fminf(a.w, b.w);
    float w = fmaxf(__fsub_rn(brx, tlx), 0.0f);
    float h = fmaxf(__fsub_rn(bry, tly), 0.0f);
    float inter = __fmul_rn(w, h);
    float aa = __fmul_rn(__fsub_rn(a.z, a.x), __fsub_rn(a.w, a.y));
    float ab = __fmul_rn(__fsub_rn(b.z, b.x), __fsub_rn(b.w, b.y));
    float uni = __fsub_rn(__fadd_rn(aa, ab), inter);
    uni = (uni > 0.0f) ? uni : 1.0f;
    return __fdiv_rn(inter, uni);
}

__device__ __forceinline__ int binof(float conf) {
    int b = (int)(__fmul_rn(conf, 1024.0f));
    return b > NBIN - 1 ? NBIN - 1 : (b < 0 ? 0 : b);
}

// biased conf bits of the smallest positive float whose bin >= B (exact).
__device__ __forceinline__ unsigned cut_for(int B) {
    if (B <= 0) return 0x80000001u;
    if (B > NBIN - 1) return 0xFFFFFFFFu;
    float g = (float)B / 1024.0f;
    for (;;) {
        float p = __int_as_float(__float_as_int(g) - 1);
        if ((int)(__fmul_rn(p, 1024.0f)) >= B) g = p; else break;
    }
    return __float_as_uint(g) ^ 0x80000000u;
}

// ---------------- K1: tile-staged score / key / histogram ------------------
__global__ void __launch_bounds__(128) k_score(const float* __restrict__ clean,
                                               const float* __restrict__ patch) {
    __shared__ float sd[TILE * 85];
    int seg   = blockIdx.y;
    int which = seg >> 3, img = seg & 7;
    int tile  = blockIdx.x;
    int tid   = threadIdx.x;
    if (seg == 0 && tile == 0 && tid == 0) { g_tot[0] = 0.0f; g_tot[1] = 0.0f; }
    const float* base = (which ? patch : clean)
                      + ((size_t)img * NROW + (size_t)tile * TILE) * 85;
    const float4* b4 = (const float4*)base;
    float4* s4 = (float4*)sd;

    {   // 2380 float4 = 18*128 + 76, MLP-batched
        float4 r[9];
        #pragma unroll
        for (int k = 0; k < 9; k++) r[k] = b4[tid + k * 128];
        #pragma unroll
        for (int k = 0; k < 9; k++) s4[tid + k * 128] = r[k];
        #pragma unroll
        for (int k = 0; k < 9; k++) r[k] = b4[tid + (9 + k) * 128];
        #pragma unroll
        for (int k = 0; k < 9; k++) s4[tid + (9 + k) * 128] = r[k];
        if (tid < 76) s4[tid + 2304] = b4[tid + 2304];
    }
    __syncthreads();

    if (tid < TILE) {
        const float* row = sd + tid * 85;
        float obj = row[4];
        float m0 = row[5], m1 = row[6], m2 = row[7], m3 = row[8];
        #pragma unroll
        for (int c = 9; c < 85; c += 4) {
            m0 = fmaxf(m0, row[c]);     m1 = fmaxf(m1, row[c + 1]);
            m2 = fmaxf(m2, row[c + 2]); m3 = fmaxf(m3, row[c + 3]);
        }
        float conf = __fmul_rn(fmaxf(fmaxf(m0, m1), fmaxf(m2, m3)), obj);
        int r = tile * TILE + tid;
        float TH = which ? 0.001f : 0.25f;
        unsigned khi = 0u, klo = 0u;
        if (obj > TH && conf > TH) {
            int cls = 0;
            for (int c = 5; c < 85; c++) {
                if (__fmul_rn(row[c], obj) == conf) { cls = c - 5; break; }
            }
            khi = __float_as_uint(conf) ^ 0x80000000u;
            klo = ((unsigned)(32767 - r) << 7) | (unsigned)cls;
            atomicAdd(&g_hist[seg][binof(conf)], 1);
        }
        g_keyhi[seg][r] = khi;                           // coalesced 4B
        g_keylo[seg][r] = klo;                           // coalesced 4B
    }
}

// ---------------- K2: threshold + gather + tie + NMS; patch computes loss ---
__global__ void __launch_bounds__(1024) k_select(const float* __restrict__ clean,
                                                 const float* __restrict__ patch,
                                                 float* __restrict__ out) {
    __shared__ union {
        struct {
            unsigned long long skey[KP];
            unsigned long long tie[1024];
            float4 obox[KP];
            short  clslist[80 * 64];
        } sel;
        struct {
            float4 pdiv[KP];
            short  plist[80 * 128];
        } loss;
    } U;
    __shared__ unsigned char keepc[KP];
    __shared__ unsigned char sclz[KP];
    __shared__ int   ccnt[80];
    __shared__ int   wsum[32];
    __shared__ float rs[32], rn2[32];
    __shared__ int   sNeed, sAllin, sNin, sNtie;
    __shared__ unsigned sCutIn, sCutTie;

    int seg = blockIdx.x;
    int which = seg >> 3, img = seg & 7;
    int K = which ? KP : KC;
    const float* src = (which ? patch : clean) + (size_t)img * NROW * 85;
    int tid = threadIdx.x, lane = tid & 31, w = tid >> 5;

    // --- Phase A: one bin per thread, descending order ---
    int s = g_hist[seg][NBIN - 1 - tid];
    int inc = s;
    #pragma unroll
    for (int off = 1; off < 32; off <<= 1) {
        int n = __shfl_up_sync(FULL, inc, off);
        if (lane >= off) inc += n;
    }
    if (lane == 31) wsum[w] = inc;
    if (tid == 0) { sNin = 0; sNtie = 0; sAllin = 0; sNeed = 0; }
    if (tid < 80) ccnt[tid] = 0;
    __syncthreads();
    if (w == 0) {
        int v = wsum[lane];
        #pragma unroll
        for (int off = 1; off < 32; off <<= 1) {
            int n = __shfl_up_sync(FULL, v, off);
            if (lane >= off) v += n;
        }
        wsum[lane] = v;
    }
    __syncthreads();
    int wbase = w ? wsum[w - 1] : 0;
    int incl = wbase + inc, excl = incl - s;
    int total = wsum[31];
    if (total <= K) {
        if (tid == 0) {
            sAllin = 1; sCutIn = 0x80000001u; sCutTie = 0x80000001u;
        }
    } else if (excl < K && incl >= K) {           // unique crossing thread
        int T = NBIN - 1 - tid;
        sNeed  = K - excl;
        sCutIn = cut_for(T + 1);
        sCutTie = cut_for(T);
    }
    g_hist[seg][tid] = 0;                          // re-zero for next replay
    __syncthreads();
    int allin = sAllin, need = sNeed;
    unsigned cutIn = sCutIn, cutTie = sCutTie;

    // --- Phase B: single-round SoA gather over hi-words ---
    const unsigned* hsrc = g_keyhi[seg];
    const unsigned* lsrc = g_keylo[seg];
    const uint4* h4 = (const uint4*)hsrc;          // NROW % 4 == 0

    // pass 1: count
    int cin = 0, cti = 0;
    #pragma unroll
    for (int q = 0; q < 7; q++) {
        int i = q * 4096 + (tid << 2);
        uint4 h;
        if (i < NROW) h = h4[q * 1024 + tid];
        else { h.x = 0; h.y = 0; h.z = 0; h.w = 0; }
        cin += (h.x >= cutIn) + (h.y >= cutIn) + (h.z >= cutIn) + (h.w >= cutIn);
        cti += (h.x >= cutTie) + (h.y >= cutTie) + (h.z >= cutTie) + (h.w >= cutTie);
    }
    cti -= cin;                                    // ties only
    int pin = cin, pti = cti;
    #pragma unroll
    for (int off = 1; off < 32; off <<= 1) {
        int a = __shfl_up_sync(FULL, pin, off);
        int b = __shfl_up_sync(FULL, pti, off);
        if (lane >= off) { pin += a; pti += b; }
    }
    int wtotin = __shfl_sync(FULL, pin, 31);
    int wtotti = __shfl_sync(FULL, pti, 31);
    int bin0 = 0, bti0 = 0;
    if (lane == 31) {
        if (wtotin) bin0 = atomicAdd(&sNin, wtotin);
        if (wtotti) bti0 = atomicAdd(&sNtie, wtotti);
    }
    bin0 = __shfl_sync(FULL, bin0, 31);
    bti0 = __shfl_sync(FULL, bti0, 31);
    int pos  = bin0 + pin - cin;
    int posT = bti0 + pti - cti;

    // pass 2: re-read (L1-hot), classify, write; lo loaded only for accepted
    if (cin | cti) {
        #pragma unroll
        for (int q = 0; q < 7; q++) {
            int i = q * 4096 + (tid << 2);
            if (i >= NROW) break;
            uint4 h = h4[q * 1024 + tid];
            unsigned hw[4] = { h.x, h.y, h.z, h.w };
            #pragma unroll
            for (int e = 0; e < 4; e++) {
                unsigned hv = hw[e];
                if (hv >= cutIn) {
                    unsigned long long key =
                        ((unsigned long long)hv << 32) | lsrc[i + e];
                    U.sel.skey[pos++] = key;
                } else if (hv >= cutTie) {
                    if (posT < 1024) {
                        unsigned long long key =
                            ((unsigned long long)hv << 32) | lsrc[i + e];
                        U.sel.tie[posT] = key;
                    }
                    posT++;
                }
            }
        }
    }
    __syncthreads();
    int nin = sNin;
    int S = nin;
    if (!allin && need > 0) {
        // tie resolve by rank-counting (keys distinct, no sort)
        int nt = sNtie; if (nt > 1024) nt = 1024;
        if (tid < nt) {
            unsigned long long k = U.sel.tie[tid];
            int rank = 0;
            for (int j = 0; j < nt; j++) rank += (U.sel.tie[j] > k);
            if (rank < need) U.sel.skey[nin + rank] = k;
        }
        S = nin + need;
    }
    __syncthreads();

    // --- Phase C: per-thread decode (cls from key; 5 loads per row) ---
    if (tid < S) {
        unsigned long long key = U.sel.skey[tid];
        unsigned lo32 = (unsigned)key;
        int cls = (int)(lo32 & 127u);
        int idx = 32767 - (int)((lo32 >> 7) & 32767u);
        const float* rp = src + (size_t)idx * 85;
        float cx = rp[0], cy = rp[1], ww2 = rp[2], hh2 = rp[3];
        float hw = __fmul_rn(ww2, 0.5f), hh = __fmul_rn(hh2, 0.5f);
        float4 pb4, ob;
        pb4.x = __fsub_rn(cx, hw); pb4.y = __fsub_rn(cy, hh);
        pb4.z = __fadd_rn(cx, hw); pb4.w = __fadd_rn(cy, hh);
        float off = (float)cls * 4096.0f;
        ob.x = __fadd_rn(pb4.x, off); ob.y = __fadd_rn(pb4.y, off);
        ob.z = __fadd_rn(pb4.z, off); ob.w = __fadd_rn(pb4.w, off);
        g_box[which][img][tid] = pb4;
        g_cls[which][img][tid] = (unsigned char)cls;
        U.sel.obox[tid] = ob;
        keepc[tid] = 1;
        sclz[tid]  = (unsigned char)cls;
        int p = atomicAdd(&ccnt[cls], 1);
        if (p < 64) U.sel.clslist[cls * 64 + p] = (short)tid;
        else if (which == 0) g_keep[0][img][tid] = 1;  // overflow: kept
    } else {
        keepc[tid] = 0;
    }
    if (which == 0)
        for (int i = S + tid; i < K; i += 1024) g_keep[0][img][i] = 0;
    __syncthreads();

    // --- Phase D: per-class NMS, one warp per class (broadcast-smem) ---
    for (int c = w; c < 80; c += 32) {
        int m = ccnt[c]; if (m > 64) m = 64;
        int base2 = c * 64;
        if (m == 0) continue;
        if (m == 1) {
            if (which == 0 && lane == 0)
                g_keep[0][img][U.sel.clslist[base2]] = 1;
            continue;
        }
        if (m <= 32) {
            int id = (lane < m) ? U.sel.clslist[base2 + lane] : -1;
            unsigned long long myk = (lane < m) ? U.sel.skey[id] : 0ull;
            int rank = 0;
            for (int j = 0; j < m; j++) {                  // broadcast LDS
                unsigned long long kj = U.sel.skey[U.sel.clslist[base2 + j]];
                rank += (kj > myk);
            }
            if (lane < m) U.sel.clslist[base2 + rank] = (short)id;
            __syncwarp();
            int ids = (lane < m) ? U.sel.clslist[base2 + lane] : -1;
            float4 B = (lane < m) ? U.sel.obox[ids] : make_float4(0.f, 0.f, 0.f, 0.f);
            unsigned keepb = (m >= 32) ? FULL : ((1u << m) - 1u);
            for (int a = 0; a < m - 1; a++) {
                if ((keepb >> a) & 1u) {
                    float4 A = U.sel.obox[U.sel.clslist[base2 + a]];  // broadcast
                    bool sup = (lane > a) && (lane < m) && ((keepb >> lane) & 1u)
                               && (iou_rn(A, B) > 0.45f);
                    keepb &= ~__ballot_sync(FULL, sup);
                }
            }
            if (lane < m) {
                unsigned char kb = (unsigned char)((keepb >> lane) & 1u);
                keepc[ids] = kb;
                if (which == 0) g_keep[0][img][ids] = kb;
            }
        } else {
            if (lane == 0) {
                for (int i2 = 1; i2 < m; i2++) {
                    short v = U.sel.clslist[base2 + i2];
                    unsigned long long kv = U.sel.skey[v];
                    int j2 = i2 - 1;
                    while (j2 >= 0 && U.sel.skey[U.sel.clslist[base2 + j2]] < kv) {
                        U.sel.clslist[base2 + j2 + 1] = U.sel.clslist[base2 + j2]; j2--;
                    }
                    U.sel.clslist[base2 + j2 + 1] = v;
                }
            }
            __syncwarp();
            for (int a = 0; a < m - 1; a++) {
                int ta = U.sel.clslist[base2 + a];
                if (keepc[ta]) {
                    float4 A = U.sel.obox[ta];
                    for (int b = a + 1 + lane; b < m; b += 32) {
                        int tb = U.sel.clslist[base2 + b];
                        if (keepc[tb] && iou_rn(A, U.sel.obox[tb]) > 0.45f) keepc[tb] = 0;
                    }
                }
                __syncwarp();
            }
            if (which == 0)
                for (int b = lane; b < m; b += 32) {
                    int tb = U.sel.clslist[base2 + b];
                    g_keep[0][img][tb] = keepc[tb];
                }
        }
    }
    __syncthreads();

    // --- Phase E: clean publishes; patch waits + computes loss ---
    if (which == 0) {
        __threadfence();
        if (tid == 0) atomicExch(&g_flag[img], 1);
        return;
    }

    if (tid == 0) { while (atomicAdd(&g_flag[img], 0) == 0) {} }
    __syncthreads();                           // clean data now visible
    if (tid < 80) ccnt[tid] = 0;
    __syncthreads();                           // safe to overlay union

    {   // patch class lists from own smem state
        float4 pb = g_box[1][img][tid];
        U.loss.pdiv[tid] = make_float4(__fdiv_rn(pb.x, 640.0f), __fdiv_rn(pb.y, 640.0f),
                                       __fdiv_rn(pb.z, 640.0f), __fdiv_rn(pb.w, 640.0f));
        if (keepc[tid]) {
            int c = sclz[tid];
            int p = atomicAdd(&ccnt[c], 1);
            if (p < 128) U.loss.plist[c * 128 + p] = (short)tid;
        }
    }
    __syncthreads();

    float ss = 0.0f, nn = 0.0f;
    if (tid < KC && g_keep[0][img][tid]) {
        nn = 1.0f;
        int c = g_cls[0][img][tid];
        float4 cb = g_box[0][img][tid];
        float4 cd = make_float4(__fdiv_rn(cb.x, 640.0f), __fdiv_rn(cb.y, 640.0f),
                                __fdiv_rn(cb.z, 640.0f), __fdiv_rn(cb.w, 640.0f));
        float tm = 0.0f;
        int m = ccnt[c]; if (m > 128) m = 128;
        int base2 = c * 128;
        for (int b2 = 0; b2 < m; b2++)
            tm = fmaxf(tm, iou_rn(cd, U.loss.pdiv[U.loss.plist[base2 + b2]]));
        ss = tm;
    }
    #pragma unroll
    for (int off = 16; off; off >>= 1) {
        ss += __shfl_down_sync(FULL, ss, off);
        nn += __shfl_down_sync(FULL, nn, off);
    }
    if (lane == 0) { rs[w] = ss; rn2[w] = nn; }
    __syncthreads();
    if (tid == 0) {
        float Sm = 0.0f, Nm = 0.0f;
        #pragma unroll
        for (int i = 0; i < 32; i++) { Sm += rs[i]; Nm += rn2[i]; }
        atomicAdd(&g_tot[0], Sm);
        atomicAdd(&g_tot[1], Nm);
        __threadfence();
        int old = atomicAdd(&g_cnt, 1);
        if (old == BIMG - 1) {
            float tot = atomicAdd(&g_tot[0], 0.0f);
            float cnt = atomicAdd(&g_tot[1], 0.0f);
            out[0] = (cnt > 0.0f) ? __fsub_rn(1.0f, __fdiv_rn(tot, fmaxf(cnt, 1.0f)))
                                  : 1.0f;
            g_cnt = 0;
        }
        g_flag[img] = 0;                       // reset for next replay
    }
}

// ---------------- launch: serial two-kernel schedule (known-good) ----------
extern "C" void kernel_launch(void* const* d_in, const int* in_sizes, int n_in,
                              void* d_out, int out_size) {
    const float* clean = (const float*)d_in[0];
    const float* patch = (const float*)d_in[1];

    dim3 sgrid(NTILE, 16);                     // 225 x 16 tiles
    k_score<<<sgrid, 128>>>(clean, patch);
    k_select<<<16, 1024>>>(clean, patch, (float*)d_out);
}